// round 17
// baseline (speedup 1.0000x reference)
#include <cuda_runtime.h>
#include <cuda.h>
#include <cuda_fp16.h>
#include <cstdint>

typedef unsigned int u32;
typedef unsigned long long u64;

#define BATCH 2048
#define NL0 1024
#define NL1 2048
#define NL2 2048

#if defined(__CUDA_ARCH__) && (defined(__CUDA_ARCH_FEAT_SM103_ALL) || \
    defined(__CUDA_ARCH_FEAT_SM100_ALL) || \
    (defined(__CUDA_ARCH_SPECIFIC__) && (__CUDA_ARCH_SPECIFIC__ >= 1000)) || \
    (defined(__CUDA_ARCH_FAMILY_SPECIFIC__) && (__CUDA_ARCH_FAMILY_SPECIFIC__ >= 1000)))
#define EQ_TC 1
#else
#define EQ_TC 0
#endif

// ---- device scratch (no-alloc rule) ----
__device__ float  g_s0f[2][(size_t)BATCH * NL0];
__device__ float  g_s1f[2][(size_t)BATCH * NL1];
__device__ float  g_s2f[2][(size_t)BATCH * NL2];
__device__ __half g_s0h[2][(size_t)BATCH * NL0], g_s0l[2][(size_t)BATCH * NL0];
__device__ __half g_s1h[2][(size_t)BATCH * NL1], g_s1l[2][(size_t)BATCH * NL1];
__device__ __half g_s2h[2][(size_t)BATCH * NL2], g_s2l[2][(size_t)BATCH * NL2];
__device__ float  g_c2[(size_t)BATCH * NL2];
__device__ __half g_dh[(size_t)BATCH * NL2], g_dl[(size_t)BATCH * NL2];
__device__ __half g_W0h[(size_t)NL0 * NL1],  g_W0l[(size_t)NL0 * NL1];
__device__ __half g_W0Th[(size_t)NL1 * NL0], g_W0Tl[(size_t)NL1 * NL0];
__device__ __half g_W1h[(size_t)NL1 * NL2],  g_W1l[(size_t)NL1 * NL2];
__device__ __half g_W1Th[(size_t)NL2 * NL1], g_W1Tl[(size_t)NL2 * NL1];
__device__ __half g_W2h[(size_t)NL2 * NL2],  g_W2l[(size_t)NL2 * NL2];
__device__ __align__(128) CUtensorMap g_tmaps[24];

#if EQ_TC
__device__ __forceinline__ u32 smem_u32(const void* p) {
    u32 a;
    asm("{ .reg .u64 t; cvta.to.shared.u64 t, %1; cvt.u32.u64 %0, t; }" : "=r"(a) : "l"(p));
    return a;
}
__device__ __forceinline__ bool elect_one() {
    u32 p;
    asm volatile("{\n\t.reg .pred p;\n\telect.sync _|p, 0xFFFFFFFF;\n\tselp.b32 %0, 1, 0, p;\n\t}" : "=r"(p));
    return p != 0;
}
__device__ __forceinline__ void mbar_wait(u32 mbar, u32 parity) {
    u32 done;
    asm volatile("{\n\t.reg .pred p;\n\t"
                 "mbarrier.try_wait.parity.acquire.cta.shared::cta.b64 p, [%1], %2;\n\t"
                 "selp.b32 %0, 1, 0, p;\n\t}" : "=r"(done) : "r"(mbar), "r"(parity) : "memory");
    while (!done)
        asm volatile("{\n\t.reg .pred p;\n\t"
                     "mbarrier.try_wait.parity.acquire.cta.shared::cta.b64 p, [%1], %2, 0x989680;\n\t"
                     "selp.b32 %0, 1, 0, p;\n\t}" : "=r"(done) : "r"(mbar), "r"(parity) : "memory");
}
__device__ __forceinline__ void mma_f16_ss(u32 d, u64 a, u64 b, u32 idesc, u32 acc) {
    asm volatile("{\n\t.reg .pred p;\n\tsetp.ne.u32 p, %5, 0;\n\t"
                 "tcgen05.mma.cta_group::1.kind::f16 [%0], %1, %2, %3, {%4, %4, %4, %4}, p;\n\t}"
                 :: "r"(d), "l"(a), "l"(b), "r"(idesc), "r"(0u), "r"(acc) : "memory");
}
__device__ __forceinline__ u64 sdesc(u32 addr) {   // SW128, v1, SBO=64, LBO=1
    return (2ull << 61) | (1ull << 46) | (64ull << 32) | (1ull << 16) | ((u64)(addr >> 4) & 0x3FFF);
}
__device__ __forceinline__ void tma2d(u32 dst, const void* map, int x, int y, u32 mbar) {
    asm volatile("cp.async.bulk.tensor.2d.shared::cta.global.tile.mbarrier::complete_tx::bytes "
                 "[%0], [%1, {%2, %3}], [%4];"
                 :: "r"(dst), "l"(map), "r"(x), "r"(y), "r"(mbar) : "memory");
}
#define TC_LD32(r, addr) \
    asm volatile("tcgen05.ld.sync.aligned.32x32b.x32.b32 " \
        "{%0, %1, %2, %3, %4, %5, %6, %7, %8, %9, %10, %11, %12, %13, %14, %15, " \
        " %16, %17, %18, %19, %20, %21, %22, %23, %24, %25, %26, %27, %28, %29, %30, %31}, [%32];" \
        : "=r"((r)[0]),  "=r"((r)[1]),  "=r"((r)[2]),  "=r"((r)[3]), \
          "=r"((r)[4]),  "=r"((r)[5]),  "=r"((r)[6]),  "=r"((r)[7]), \
          "=r"((r)[8]),  "=r"((r)[9]),  "=r"((r)[10]), "=r"((r)[11]), \
          "=r"((r)[12]), "=r"((r)[13]), "=r"((r)[14]), "=r"((r)[15]), \
          "=r"((r)[16]), "=r"((r)[17]), "=r"((r)[18]), "=r"((r)[19]), \
          "=r"((r)[20]), "=r"((r)[21]), "=r"((r)[22]), "=r"((r)[23]), \
          "=r"((r)[24]), "=r"((r)[25]), "=r"((r)[26]), "=r"((r)[27]), \
          "=r"((r)[28]), "=r"((r)[29]), "=r"((r)[30]), "=r"((r)[31]) \
        : "r"(addr))
#endif  // EQ_TC

// ---- fused prep: all decomposes (+ fp32 state copies) in ONE launch ----
__device__ __forceinline__ void dec4(const float4 x, __half2* hi, __half2* lo, int clampv) {
    float4 y = x;
    if (clampv) {
        y.x = fminf(fmaxf(y.x, 0.f), 1.f); y.y = fminf(fmaxf(y.y, 0.f), 1.f);
        y.z = fminf(fmaxf(y.z, 0.f), 1.f); y.w = fminf(fmaxf(y.w, 0.f), 1.f);
    }
    __half h0 = __float2half_rn(y.x), h1 = __float2half_rn(y.y);
    __half h2 = __float2half_rn(y.z), h3 = __float2half_rn(y.w);
    hi[0] = __halves2half2(h0, h1);
    hi[1] = __halves2half2(h2, h3);
    lo[0] = __halves2half2(__float2half_rn(y.x - __half2float(h0)),
                           __float2half_rn(y.y - __half2float(h1)));
    lo[1] = __halves2half2(__float2half_rn(y.z - __half2float(h2)),
                           __float2half_rn(y.w - __half2float(h3)));
}

__global__ void decompose_all(const float* __restrict__ s0, const float* __restrict__ s1,
                              const float* __restrict__ s2, const float* __restrict__ data,
                              const float* __restrict__ W0, const float* __restrict__ W1,
                              const float* __restrict__ W2) {
    const size_t q0 = (size_t)BATCH * NL0 / 4;           // s0
    const size_t q1 = q0 + (size_t)BATCH * NL1 / 4;      // s1
    const size_t q2 = q1 + (size_t)BATCH * NL2 / 4;      // s2
    const size_t q3 = q2 + (size_t)BATCH * NL2 / 4;      // data
    const size_t q4 = q3 + (size_t)NL0 * NL1 / 4;        // W0
    const size_t q5 = q4 + (size_t)NL1 * NL2 / 4;        // W1
    const size_t q6 = q5 + (size_t)NL2 * NL2 / 4;        // W2
    size_t i = (size_t)blockIdx.x * blockDim.x + threadIdx.x;
    if (i >= q6) return;
    const float* src; __half* hi; __half* lo; float* fcpy = nullptr; size_t off; int clampv = 0;
    if (i < q0)      { off = i;      src = s0;   hi = g_s0h[0]; lo = g_s0l[0]; fcpy = g_s0f[0]; }
    else if (i < q1) { off = i - q0; src = s1;   hi = g_s1h[0]; lo = g_s1l[0]; fcpy = g_s1f[0]; }
    else if (i < q2) { off = i - q1; src = s2;   hi = g_s2h[0]; lo = g_s2l[0]; fcpy = g_s2f[0]; }
    else if (i < q3) { off = i - q2; src = data; hi = g_dh;     lo = g_dl;     clampv = 1; }
    else if (i < q4) { off = i - q3; src = W0;   hi = g_W0h;    lo = g_W0l; }
    else if (i < q5) { off = i - q4; src = W1;   hi = g_W1h;    lo = g_W1l; }
    else             { off = i - q5; src = W2;   hi = g_W2h;    lo = g_W2l; }
    float4 x = reinterpret_cast<const float4*>(src)[off];
    if (fcpy) reinterpret_cast<float4*>(fcpy)[off] = x;
    dec4(x, reinterpret_cast<__half2*>(hi) + 2 * off, reinterpret_cast<__half2*>(lo) + 2 * off, clampv);
}

__global__ void transpose_decompose_k(const float* __restrict__ in,
                                      __half* __restrict__ oh, __half* __restrict__ ol,
                                      int R, int C) {
    __shared__ float t[32][33];
    int c0 = blockIdx.x * 32, r0 = blockIdx.y * 32;
    int tx = threadIdx.x, ty = threadIdx.y;   // (32,8)
#pragma unroll
    for (int i = 0; i < 32; i += 8)
        t[ty + i][tx] = in[(size_t)(r0 + ty + i) * C + (c0 + tx)];
    __syncthreads();
#pragma unroll
    for (int i = 0; i < 32; i += 8) {
        float x = t[tx][ty + i];
        __half h = __float2half_rn(x);
        size_t o = (size_t)(c0 + ty + i) * R + (r0 + tx);
        oh[o] = h; ol[o] = __float2half_rn(x - __half2float(h));
    }
}

__global__ void pack_out(float* __restrict__ out, const float* __restrict__ a,
                         const float* __restrict__ b, const float* __restrict__ c) {
    const size_t n0 = (size_t)BATCH * NL0, n1 = (size_t)BATCH * NL1, n2 = (size_t)BATCH * NL2;
    size_t stride = (size_t)gridDim.x * blockDim.x;
    for (size_t i = (size_t)blockIdx.x * blockDim.x + threadIdx.x; i < n0 + n1 + n2; i += stride)
        out[i] = (i < n0) ? a[i] : (i < n0 + n1) ? b[i - n0] : c[i - n0 - n1];
}

// ---------------------------------------------------------------------------
// FUSED step kernel: one launch computes ALL tiles of a step (G1+G2+G3), or
// c2 in c2-mode. Tile decode from blockIdx.x; BN=256 everywhere; per-tile body
// is the proven R13 pipeline (K64 chunks, SW128, TMA, 2-stage ring, warp-0
// MMA via SS cg1 tcgen05 kind::f16, 3 split products, fused epilogue).
// Step-mode tile order: G2 (longest K) first for wave balance.
// ---------------------------------------------------------------------------
__global__ void __launch_bounds__(256, 1) gemm_step(
    const CUtensorMap* M, const float* __restrict__ b0, const float* __restrict__ b1,
    const float* __restrict__ b2, int cu, int c2mode)
{
    extern __shared__ char smem_raw[];
    const int nx = cu ^ 1;
    // ---- tile decode ----
    int g, i;
    if (c2mode) { g = 3; i = blockIdx.x; }
    else {
        int t = blockIdx.x;
        if (t < 128)      { g = 1; i = t; }
        else if (t < 256) { g = 2; i = t - 128; }
        else              { g = 0; i = t - 256; }
    }
    const int tilesx = (g == 0) ? 4 : 8;
    const int nBase = (i % tilesx) * 256;
    const int mBase = (i / tilesx) * 128;
    // ---- operand selection ----
    int iAh, iAl, iBh, iBl, iA2h = 0, iA2l = 0, iB2h = 0, iB2l = 0;
    int K0, K1 = 0, N;
    const float *bias, *prev = nullptr, *extra = nullptr;
    float* Cf; __half *Ch = nullptr, *Cl = nullptr;
    if (g == 0) {        // n0 = clip(.8 s0 + .2 (s1@W0^T + b0))
        iAh = 4 + cu; iAl = 6 + cu; iBh = 14; iBl = 15; K0 = NL1; N = NL0; bias = b0;
        prev = g_s0f[cu]; Cf = g_s0f[nx]; Ch = g_s0h[nx]; Cl = g_s0l[nx];
    } else if (g == 1) { // n1 = clip(.8 s1 + .2 (s2@W1^T + s0@W0 + b1))
        iAh = 8 + cu; iAl = 10 + cu; iBh = 18; iBl = 19; K0 = NL2;
        iA2h = 0 + cu; iA2l = 2 + cu; iB2h = 16; iB2l = 17; K1 = NL0;
        N = NL1; bias = b1; prev = g_s1f[cu]; Cf = g_s1f[nx]; Ch = g_s1h[nx]; Cl = g_s1l[nx];
    } else if (g == 2) { // n2 = clip(.8 s2 + .2 (c2 + s1@W1))
        iAh = 4 + cu; iAl = 6 + cu; iBh = 20; iBl = 21; K0 = NL1; N = NL2; bias = nullptr;
        prev = g_s2f[cu]; extra = g_c2; Cf = g_s2f[nx]; Ch = g_s2h[nx]; Cl = g_s2l[nx];
    } else {             // c2 = clip(data)@W2^T + b2
        iAh = 12; iAl = 13; iBh = 22; iBl = 23; K0 = NL2; N = NL2; bias = b2; Cf = g_c2;
    }

#if EQ_TC
    constexpr int STAGE = 32768 + 65536;          // Ah,Al (16K each) + Bh,Bl (32K each)
    const int tid = threadIdx.x, wid = tid >> 5, lid = tid & 31;
    u32 sb = (smem_u32(smem_raw) + 1023) & ~1023u;

    if (wid == 0)
        asm volatile("tcgen05.alloc.cta_group::1.sync.aligned.shared::cta.b32 [%0], 512;"
                     :: "r"(sb) : "memory");
    if (tid == 0) {
        asm volatile("mbarrier.init.shared.b64 [%0], 1;" :: "r"(sb + 16) : "memory");  // full0
        asm volatile("mbarrier.init.shared.b64 [%0], 1;" :: "r"(sb + 24) : "memory");  // full1
        asm volatile("mbarrier.init.shared.b64 [%0], 1;" :: "r"(sb + 32) : "memory");  // cmt0
        asm volatile("mbarrier.init.shared.b64 [%0], 1;" :: "r"(sb + 40) : "memory");  // cmt1
    }
    __syncthreads();
    u32 tmem;
    asm volatile("ld.shared.b32 %0, [%1];" : "=r"(tmem) : "r"(sb));

    const int nkb0 = K0 >> 6, nkb = nkb0 + (K1 >> 6);
    const u32 idesc = 0x10u | (32u << 17) | (8u << 24);   // f32 acc, f16 A/B, M=128, N=256

    if (wid == 0) {
        auto load_chunk = [&](int kb) {
            const int s = kb & 1;
            const CUtensorMap *Ah, *Al, *Bh, *Bl; int koff;
            if (kb < nkb0) { Ah = M + iAh;  Al = M + iAl;  Bh = M + iBh;  Bl = M + iBl;  koff = kb << 6; }
            else           { Ah = M + iA2h; Al = M + iA2l; Bh = M + iB2h; Bl = M + iB2l; koff = (kb - nkb0) << 6; }
            const u32 stg = sb + 1024 + s * STAGE;
            const u32 full = sb + 16 + 8 * s;
            asm volatile("mbarrier.arrive.expect_tx.shared.b64 _, [%0], %1;"
                         :: "r"(full), "r"((u32)STAGE) : "memory");
            tma2d(stg,         Ah, koff, mBase, full);
            tma2d(stg + 16384, Al, koff, mBase, full);
            tma2d(stg + 32768, Bh, koff, nBase, full);
            tma2d(stg + 65536, Bl, koff, nBase, full);
        };
        if (elect_one()) { load_chunk(0); if (nkb > 1) load_chunk(1); }
        for (int kb = 0; kb < nkb; ++kb) {
            const int s = kb & 1;
            const u32 par = (u32)((kb >> 1) & 1);
            mbar_wait(sb + 16 + 8 * s, par);
            if (elect_one()) {
                const u32 stg = sb + 1024 + s * STAGE;
                u64 dAh = sdesc(stg), dAl = sdesc(stg + 16384);
                u64 dBh = sdesc(stg + 32768), dBl = sdesc(stg + 65536);
#pragma unroll
                for (int ks = 0; ks < 4; ++ks) {
                    mma_f16_ss(tmem, dAh + ks * 2, dBh + ks * 2, idesc, (kb > 0) || (ks > 0));
                    mma_f16_ss(tmem, dAh + ks * 2, dBl + ks * 2, idesc, 1);
                    mma_f16_ss(tmem, dAl + ks * 2, dBh + ks * 2, idesc, 1);
                }
                asm volatile("tcgen05.commit.cta_group::1.mbarrier::arrive::one.shared::cluster.b64 [%0];"
                             :: "r"(sb + 32 + 8 * s) : "memory");
            }
            mbar_wait(sb + 32 + 8 * s, par);
            if (kb + 2 < nkb && elect_one()) load_chunk(kb + 2);
        }
    }
    __syncthreads();
    mbar_wait(sb + 32 + 8 * ((nkb - 1) & 1), (u32)(((nkb - 1) >> 1) & 1));
    asm volatile("tcgen05.fence::after_thread_sync;" ::: "memory");

    // Epilogue: warps 0-3 cols [0,128), warps 4-7 cols [128,256).
    const int row = mBase + (wid & 3) * 32 + lid;
    const int ch0 = (wid >> 2) * 128;
#pragma unroll
    for (int gg = 0; gg < 4; ++gg) {
        const int c0 = ch0 + gg * 32;
        u32 r_[32];
        TC_LD32(r_, tmem + c0);
        asm volatile("tcgen05.wait::ld.sync.aligned;" ::: "memory");
        float v[32];
#pragma unroll
        for (int j = 0; j < 32; ++j) v[j] = __uint_as_float(r_[j]);
        const size_t base = (size_t)row * N + nBase + c0;
        if (bias)
#pragma unroll
            for (int j = 0; j < 32; ++j) v[j] += __ldg(bias + nBase + c0 + j);
        if (prev) {
#pragma unroll
            for (int q = 0; q < 8; ++q) {
                float4 p = *reinterpret_cast<const float4*>(prev + base + q * 4);
                float4 e = make_float4(0.f, 0.f, 0.f, 0.f);
                if (extra) e = *reinterpret_cast<const float4*>(extra + base + q * 4);
                v[4*q+0] = fminf(fmaxf(0.8f * p.x + 0.2f * (v[4*q+0] + e.x), 0.f), 1.f);
                v[4*q+1] = fminf(fmaxf(0.8f * p.y + 0.2f * (v[4*q+1] + e.y), 0.f), 1.f);
                v[4*q+2] = fminf(fmaxf(0.8f * p.z + 0.2f * (v[4*q+2] + e.z), 0.f), 1.f);
                v[4*q+3] = fminf(fmaxf(0.8f * p.w + 0.2f * (v[4*q+3] + e.w), 0.f), 1.f);
            }
        }
#pragma unroll
        for (int q = 0; q < 8; ++q)
            *reinterpret_cast<float4*>(Cf + base + q * 4) =
                make_float4(v[4*q+0], v[4*q+1], v[4*q+2], v[4*q+3]);
        if (Ch)
#pragma unroll
            for (int j = 0; j < 32; j += 2) {
                __half h0 = __float2half_rn(v[j]), h1 = __float2half_rn(v[j+1]);
                *reinterpret_cast<__half2*>(Ch + base + j) = __halves2half2(h0, h1);
                *reinterpret_cast<__half2*>(Cl + base + j) = __halves2half2(
                    __float2half_rn(v[j] - __half2float(h0)),
                    __float2half_rn(v[j+1] - __half2float(h1)));
            }
    }
    asm volatile("tcgen05.fence::before_thread_sync;" ::: "memory");
    __syncthreads();
    if (tid == 0) {
        asm volatile("mbarrier.inval.shared.b64 [%0];" :: "r"(sb + 16) : "memory");
        asm volatile("mbarrier.inval.shared.b64 [%0];" :: "r"(sb + 24) : "memory");
        asm volatile("mbarrier.inval.shared.b64 [%0];" :: "r"(sb + 32) : "memory");
        asm volatile("mbarrier.inval.shared.b64 [%0];" :: "r"(sb + 40) : "memory");
    }
    __syncthreads();
    if (wid == 0)
        asm volatile("tcgen05.dealloc.cta_group::1.sync.aligned.b32 %0, 512;" :: "r"(tmem));
#else
    // ---------------- SIMT fp32 fallback (non-arch-specific pass) -----------
    (void)M;
    const __half *rAh, *rAl, *rBh, *rBl, *rA2h = nullptr, *rA2l = nullptr,
                 *rB2h = nullptr, *rB2l = nullptr;
    if (g == 0)      { rAh = g_s1h[cu]; rAl = g_s1l[cu]; rBh = g_W0h;  rBl = g_W0l; }
    else if (g == 1) { rAh = g_s2h[cu]; rAl = g_s2l[cu]; rBh = g_W1h;  rBl = g_W1l;
                       rA2h = g_s0h[cu]; rA2l = g_s0l[cu]; rB2h = g_W0Th; rB2l = g_W0Tl; }
    else if (g == 2) { rAh = g_s1h[cu]; rAl = g_s1l[cu]; rBh = g_W1Th; rBl = g_W1Tl; }
    else             { rAh = g_dh;      rAl = g_dl;      rBh = g_W2h;  rBl = g_W2l; }

    float* As = reinterpret_cast<float*>(smem_raw);        // [16][132]
    float* Bs = As + 16 * 132;
    const int tid = threadIdx.x;
    const int tx = tid & 15, ty = tid >> 4;
    const int nkb0f = K0 >> 4, nkbf = nkb0f + (K1 >> 4);
    const int lrow = tid >> 1, seg8 = tid & 1;

    for (int half = 0; half < 2; ++half) {
        const int nB = nBase + half * 128;
        float acc[8][8];
#pragma unroll
        for (int a = 0; a < 8; ++a)
#pragma unroll
            for (int b = 0; b < 8; ++b) acc[a][b] = 0.f;
        for (int kb = 0; kb < nkbf; ++kb) {
            const __half *Ah, *Al, *Bh, *Bl; int ldk, koff;
            if (kb < nkb0f) { Ah = rAh;  Al = rAl;  Bh = rBh;  Bl = rBl;  ldk = K0; koff = kb << 4; }
            else            { Ah = rA2h; Al = rA2l; Bh = rB2h; Bl = rB2l; ldk = K1; koff = (kb - nkb0f) << 4; }
            {
                size_t off = (size_t)(mBase + lrow) * ldk + koff + seg8 * 8;
                uint4 hv = *reinterpret_cast<const uint4*>(Ah + off);
                uint4 lv = *reinterpret_cast<const uint4*>(Al + off);
                const __half2* hh = reinterpret_cast<const __half2*>(&hv);
                const __half2* ll = reinterpret_cast<const __half2*>(&lv);
#pragma unroll
                for (int p = 0; p < 4; ++p) {
                    float2 hf = __half22float2(hh[p]);
                    float2 lf = __half22float2(ll[p]);
                    As[(seg8 * 8 + 2 * p + 0) * 132 + lrow] = hf.x + lf.x;
                    As[(seg8 * 8 + 2 * p + 1) * 132 + lrow] = hf.y + lf.y;
                }
                off = (size_t)(nB + lrow) * ldk + koff + seg8 * 8;
                hv = *reinterpret_cast<const uint4*>(Bh + off);
                lv = *reinterpret_cast<const uint4*>(Bl + off);
#pragma unroll
                for (int p = 0; p < 4; ++p) {
                    float2 hf = __half22float2(hh[p]);
                    float2 lf = __half22float2(ll[p]);
                    Bs[(seg8 * 8 + 2 * p + 0) * 132 + lrow] = hf.x + lf.x;
                    Bs[(seg8 * 8 + 2 * p + 1) * 132 + lrow] = hf.y + lf.y;
                }
            }
            __syncthreads();
#pragma unroll
            for (int kk = 0; kk < 16; ++kk) {
                float a[8], b[8];
#pragma unroll
                for (int x = 0; x < 8; ++x) a[x] = As[kk * 132 + ty * 8 + x];
#pragma unroll
                for (int y = 0; y < 8; ++y) b[y] = Bs[kk * 132 + tx * 8 + y];
#pragma unroll
                for (int x = 0; x < 8; ++x)
#pragma unroll
                    for (int y = 0; y < 8; ++y) acc[x][y] += a[x] * b[y];
            }
            __syncthreads();
        }
#pragma unroll
        for (int x = 0; x < 8; ++x) {
            int r = mBase + ty * 8 + x;
            size_t base = (size_t)r * N + nB + tx * 8;
#pragma unroll
            for (int y = 0; y < 8; ++y) {
                float v = acc[x][y];
                if (bias) v += bias[nB + tx * 8 + y];
                if (prev) {
                    float e = extra ? extra[base + y] : 0.f;
                    v = fminf(fmaxf(0.8f * prev[base + y] + 0.2f * (v + e), 0.f), 1.f);
                }
                Cf[base + y] = v;
                if (Ch) {
                    __half h = __float2half_rn(v);
                    Ch[base + y] = h;
                    Cl[base + y] = __float2half_rn(v - __half2float(h));
                }
            }
        }
    }
#endif
}

// ---------------------------------------------------------------------------
typedef CUresult (*PFN_tmapenc)(CUtensorMap*, CUtensorMapDataType, cuuint32_t, void*,
                                const cuuint64_t*, const cuuint64_t*, const cuuint32_t*,
                                const cuuint32_t*, CUtensorMapInterleave, CUtensorMapSwizzle,
                                CUtensorMapL2promotion, CUtensorMapFloatOOBfill);

static void enc_map(PFN_tmapenc enc, CUtensorMap* m, const void* base,
                    uint64_t K, uint64_t R, uint32_t boxR) {
    cuuint64_t dims[2]    = {K, R};
    cuuint64_t strides[1] = {K * 2};
    cuuint32_t box[2]     = {64, boxR};
    cuuint32_t es[2]      = {1, 1};
    enc(m, CU_TENSOR_MAP_DATA_TYPE_FLOAT16, 2, const_cast<void*>(base),
        dims, strides, box, es, CU_TENSOR_MAP_INTERLEAVE_NONE,
        CU_TENSOR_MAP_SWIZZLE_128B, CU_TENSOR_MAP_L2_PROMOTION_L2_128B,
        CU_TENSOR_MAP_FLOAT_OOB_FILL_NONE);
}

extern "C" void kernel_launch(void* const* d_in, const int* in_sizes, int n_in,
                              void* d_out, int out_size) {
    (void)in_sizes; (void)n_in; (void)out_size;
    const float* s0   = (const float*)d_in[0];
    const float* s1   = (const float*)d_in[1];
    const float* s2   = (const float*)d_in[2];
    const float* data = (const float*)d_in[3];
    const float* W0   = (const float*)d_in[4];
    const float* b0   = (const float*)d_in[5];
    const float* W1   = (const float*)d_in[6];
    const float* b1   = (const float*)d_in[7];
    const float* W2   = (const float*)d_in[8];
    const float* b2   = (const float*)d_in[9];

    float *s0f, *s1f, *s2f, *c2;
    __half *s0h, *s0l, *s1h, *s1l, *s2h, *s2l, *dh, *dl;
    __half *W0h, *W0l, *W0Th, *W0Tl, *W1h, *W1l, *W1Th, *W1Tl, *W2h, *W2l;
    cudaGetSymbolAddress((void**)&s0f, g_s0f);   cudaGetSymbolAddress((void**)&s1f, g_s1f);
    cudaGetSymbolAddress((void**)&s2f, g_s2f);   cudaGetSymbolAddress((void**)&c2,  g_c2);
    cudaGetSymbolAddress((void**)&s0h, g_s0h);   cudaGetSymbolAddress((void**)&s0l, g_s0l);
    cudaGetSymbolAddress((void**)&s1h, g_s1h);   cudaGetSymbolAddress((void**)&s1l, g_s1l);
    cudaGetSymbolAddress((void**)&s2h, g_s2h);   cudaGetSymbolAddress((void**)&s2l, g_s2l);
    cudaGetSymbolAddress((void**)&dh,  g_dh);    cudaGetSymbolAddress((void**)&dl,  g_dl);
    cudaGetSymbolAddress((void**)&W0h, g_W0h);   cudaGetSymbolAddress((void**)&W0l, g_W0l);
    cudaGetSymbolAddress((void**)&W0Th, g_W0Th); cudaGetSymbolAddress((void**)&W0Tl, g_W0Tl);
    cudaGetSymbolAddress((void**)&W1h, g_W1h);   cudaGetSymbolAddress((void**)&W1l, g_W1l);
    cudaGetSymbolAddress((void**)&W1Th, g_W1Th); cudaGetSymbolAddress((void**)&W1Tl, g_W1Tl);
    cudaGetSymbolAddress((void**)&W2h, g_W2h);   cudaGetSymbolAddress((void**)&W2l, g_W2l);

    const size_t n0 = (size_t)BATCH * NL0, n1 = (size_t)BATCH * NL1, n2 = (size_t)BATCH * NL2;

    // ---- tensormaps ----
    PFN_tmapenc enc = nullptr;
    cudaDriverEntryPointQueryResult qr;
    cudaGetDriverEntryPointByVersion("cuTensorMapEncodeTiled", (void**)&enc, 12000,
                                     cudaEnableDefault, &qr);
    static CUtensorMap h_maps[24];
    enc_map(enc, &h_maps[0],  s0h,      NL0, BATCH, 128);
    enc_map(enc, &h_maps[1],  s0h + n0, NL0, BATCH, 128);
    enc_map(enc, &h_maps[2],  s0l,      NL0, BATCH, 128);
    enc_map(enc, &h_maps[3],  s0l + n0, NL0, BATCH, 128);
    enc_map(enc, &h_maps[4],  s1h,      NL1, BATCH, 128);
    enc_map(enc, &h_maps[5],  s1h + n1, NL1, BATCH, 128);
    enc_map(enc, &h_maps[6],  s1l,      NL1, BATCH, 128);
    enc_map(enc, &h_maps[7],  s1l + n1, NL1, BATCH, 128);
    enc_map(enc, &h_maps[8],  s2h,      NL2, BATCH, 128);
    enc_map(enc, &h_maps[9],  s2h + n2, NL2, BATCH, 128);
    enc_map(enc, &h_maps[10], s2l,      NL2, BATCH, 128);
    enc_map(enc, &h_maps[11], s2l + n2, NL2, BATCH, 128);
    enc_map(enc, &h_maps[12], dh,       NL2, BATCH, 128);
    enc_map(enc, &h_maps[13], dl,       NL2, BATCH, 128);
    enc_map(enc, &h_maps[14], W0h,  NL1, NL0, 256);
    enc_map(enc, &h_maps[15], W0l,  NL1, NL0, 256);
    enc_map(enc, &h_maps[16], W0Th, NL0, NL1, 256);
    enc_map(enc, &h_maps[17], W0Tl, NL0, NL1, 256);
    enc_map(enc, &h_maps[18], W1h,  NL2, NL1, 256);
    enc_map(enc, &h_maps[19], W1l,  NL2, NL1, 256);
    enc_map(enc, &h_maps[20], W1Th, NL1, NL2, 256);
    enc_map(enc, &h_maps[21], W1Tl, NL1, NL2, 256);
    enc_map(enc, &h_maps[22], W2h,  NL2, NL2, 256);
    enc_map(enc, &h_maps[23], W2l,  NL2, NL2, 256);
    void* d_tm;
    cudaGetSymbolAddress(&d_tm, g_tmaps);
    cudaMemcpyAsync(d_tm, h_maps, sizeof(h_maps), cudaMemcpyHostToDevice);
    const CUtensorMap* M = (const CUtensorMap*)d_tm;

    constexpr int SM = 2048 + 2 * (32768 + 65536);   // 198,656 B
    cudaFuncSetAttribute(gemm_step, cudaFuncAttributeMaxDynamicSharedMemorySize, SM);

    // prep (kernel launches #1-#3): fused decompose+copy, two transposes
    const size_t tot4 = (n0 + 3 * n2 + (size_t)NL0 * NL1 + (size_t)NL1 * NL2 + (size_t)NL2 * NL2) / 4;
    decompose_all<<<(int)((tot4 + 255) / 256), 256>>>(s0, s1, s2, data, W0, W1, W2);
    dim3 tb(32, 8);
    transpose_decompose_k<<<dim3(NL1 / 32, NL0 / 32), tb>>>(W0, W0Th, W0Tl, NL0, NL1);
    transpose_decompose_k<<<dim3(NL2 / 32, NL1 / 32), tb>>>(W1, W1Th, W1Tl, NL1, NL2);

    // #4: c2; #5: step t=0; #6: step t=1  <- ncu (-s 5 -c 1) lands on a steady-state step
    gemm_step<<<128, 256, SM>>>(M, b0, b1, b2, 0, 1);
    for (int t = 0; t < 30; ++t)
        gemm_step<<<320, 256, SM>>>(M, b0, b1, b2, t & 1, 0);

    pack_out<<<2048, 256>>>((float*)d_out, s0f, s1f, s2f);   // final in buffer 0
}